// round 1
// baseline (speedup 1.0000x reference)
#include <cuda_runtime.h>
#include <math.h>

#define BB 4
#define TT 2048
#define CC 48
#define DD 512
#define LL 16
#define KK 9
#define CSZ 15
#define NTR 15
#define NCAND 45
#define WINLEN 19
#define TP8 (TT + 8)

// ------------------- device scratch (static, no allocs) -------------------
__device__ float g_prob[BB * TT * CC];
__device__ float g_lse[BB * TT];
__device__ float g_ent2[BB * TT];
__device__ float g_cross[BB * 9 * TP8];
__device__ float g_score[BB * TT];
__device__ int   g_pse[BB * TT];
__device__ float g_fr_part[BB];
__device__ float g_glc_part[BB * LL];

// ------------------- K1: softmax rows + lse + ent2 ------------------------
// one warp per (b,t) row of 48 channels
__global__ void k1_softmax(const float* __restrict__ fr) {
    int gw = (blockIdx.x * blockDim.x + threadIdx.x) >> 5;
    int lane = threadIdx.x & 31;
    if (gw >= BB * TT) return;
    const float* row = fr + (size_t)gw * CC;
    float x0 = row[lane];
    float x1 = (lane < 16) ? row[lane + 32] : -INFINITY;
    float m = fmaxf(x0, x1);
    #pragma unroll
    for (int o = 16; o > 0; o >>= 1) m = fmaxf(m, __shfl_xor_sync(0xffffffffu, m, o));
    float e0 = __expf(x0 - m);
    float e1 = (lane < 16) ? __expf(x1 - m) : 0.f;
    float s = e0 + e1;
    #pragma unroll
    for (int o = 16; o > 0; o >>= 1) s += __shfl_xor_sync(0xffffffffu, s, o);
    float inv = 1.f / s;
    float p0 = e0 * inv, p1 = e1 * inv;
    float ent = (p0 > 0.f) ? p0 * __log2f(p0) : 0.f;
    if (lane < 16) ent += (p1 > 0.f) ? p1 * __log2f(p1) : 0.f;
    #pragma unroll
    for (int o = 16; o > 0; o >>= 1) ent += __shfl_xor_sync(0xffffffffu, ent, o);
    float* pr = g_prob + (size_t)gw * CC;
    pr[lane] = p0;
    if (lane < 16) pr[lane + 32] = p1;
    if (lane == 0) {
        g_lse[gw] = m + __logf(s);
        g_ent2[gw] = ent;
    }
}

// ------------------- K2: crossD[d][rmin] -----------------------------------
// cross(r, r+d) = sum_c s*log2(s/2 + 1e-32), s = P(r)+P(r+d), P==0 outside [0,T)
// one warp per (b, d, rmin+4)
__global__ void k2_cross() {
    int gw = (blockIdx.x * blockDim.x + threadIdx.x) >> 5;
    int lane = threadIdx.x & 31;
    const int ntask = BB * 9 * TP8;
    if (gw >= ntask) return;
    int b = gw / (9 * TP8);
    int rem = gw % (9 * TP8);
    int d = rem / TP8;
    int r4 = rem % TP8;
    int r1 = r4 - 4;
    int r2 = r1 + d;
    const float* base = g_prob + (size_t)b * TT * CC;
    float acc = 0.f;
    #pragma unroll
    for (int h = 0; h < 2; h++) {
        int c = lane + 32 * h;
        if (c < CC) {
            float a = (r1 >= 0 && r1 < TT) ? base[r1 * CC + c] : 0.f;
            float bb = (r2 >= 0 && r2 < TT) ? base[r2 * CC + c] : 0.f;
            float sv = a + bb;
            acc += sv * __log2f(0.5f * sv + 1e-32f);   // sv==0 -> 0*finite = 0
        }
    }
    #pragma unroll
    for (int o = 16; o > 0; o >>= 1) acc += __shfl_xor_sync(0xffffffffu, acc, o);
    if (lane == 0) g_cross[(b * 9 + d) * TP8 + r4] = acc;
}

// ------------------- K3: boundary score per (b,t) --------------------------
__global__ void k3_score() {
    int idx = blockIdx.x * blockDim.x + threadIdx.x;
    if (idx >= BB * TT) return;
    int b = idx / TT;
    int t = idx % TT;
    float ent[KK];
    #pragma unroll
    for (int i = 0; i < KK; i++) {
        int r = t - 4 + i;
        ent[i] = (r >= 0 && r < TT) ? g_ent2[b * TT + r] : 0.f;
    }
    const float* cr = g_cross + (size_t)b * 9 * TP8;
    float acc = 0.f;
    #pragma unroll
    for (int i = 0; i < KK; i++) {
        #pragma unroll
        for (int j = 0; j < KK; j++) {
            if (i == 4 && j == 4) continue;
            float kv = ((i < 4) == (j < 4)) ? 1.f : -1.f;
            int d = (j > i) ? (j - i) : (i - j);
            int rmin = t - 4 + ((i < j) ? i : j);
            float cross = cr[d * TP8 + rmin + 4];
            float val = 1.f - (ent[i] + ent[j] - cross);  // val = 1 - S2 (base-2 JS*2)
            acc += kv * val;
        }
    }
    float sc = acc * (1.f / 81.f);
    if (t == 0) sc = -INFINITY;
    g_score[idx] = sc;
}

// ------------------- K4: per-batch detect (cand pick, cls, DP, pse, ce) ----
__global__ void k4_detect(const float* __restrict__ fr_logit,
                          const int* __restrict__ transcript) {
    __shared__ float ss[TT];
    __shared__ float rv[256];
    __shared__ int ri[256];
    __shared__ int scand[NCAND];
    __shared__ int s_tr[LL];
    __shared__ float scls[NTR * NCAND];
    __shared__ signed char sdir[NCAND * 31];
    __shared__ int sbdy[NTR];
    __shared__ float sred[256];

    int b = blockIdx.x;
    int tid = threadIdx.x;

    for (int t = tid; t < TT; t += 256) ss[t] = g_score[b * TT + t];
    if (tid < LL) s_tr[tid] = transcript[b * LL + tid];
    __syncthreads();

    // ---- iterative argmax + window suppression (first-index tie-break) ----
    for (int it = 0; it < NCAND; it++) {
        float bv = -INFINITY;
        int bi = 0x7fffffff;
        for (int t = tid; t < TT; t += 256) {
            float v = ss[t];
            if (v > bv) { bv = v; bi = t; }
        }
        rv[tid] = bv; ri[tid] = bi;
        __syncthreads();
        for (int s = 128; s > 0; s >>= 1) {
            if (tid < s) {
                if (rv[tid + s] > rv[tid] ||
                    (rv[tid + s] == rv[tid] && ri[tid + s] < ri[tid])) {
                    rv[tid] = rv[tid + s]; ri[tid] = ri[tid + s];
                }
            }
            __syncthreads();
        }
        int pick = ri[0];
        if (tid == 0) scand[it] = pick;
        for (int t = tid; t < TT; t += 256) {
            int dd = t - pick; if (dd < 0) dd = -dd;
            if (dd <= WINLEN) ss[t] = -INFINITY;
        }
        __syncthreads();
    }

    // ---- sort candidates ascending ----
    if (tid == 0) {
        for (int i = 1; i < NCAND; i++) {
            int v = scand[i]; int j = i - 1;
            while (j >= 0 && scand[j] > v) { scand[j + 1] = scand[j]; j--; }
            scand[j + 1] = v;
        }
    }
    __syncthreads();

    // ---- cls[tr][cand] = sum_s k0*(P[r][c_t]-P[r][c_{t+1}])/30 + backup[cand]
    const float* pb = g_prob + (size_t)b * TT * CC;
    for (int e = tid; e < NTR * NCAND; e += 256) {
        int tr_i = e / NCAND;
        int n = e % NCAND;
        int cn = scand[n];
        int ca = s_tr[tr_i], cb = s_tr[tr_i + 1];
        float sacc = 0.f;
        #pragma unroll
        for (int sft = 0; sft < CSZ; sft++) {
            int r = cn + sft - 7;
            if (r >= 0 && r < TT) {
                float sign = (sft < 7) ? 1.f : -1.f;
                sacc += sign * (pb[r * CC + ca] - pb[r * CC + cb]);
            }
        }
        scls[e] = sacc * (1.f / 30.f) + g_score[b * TT + cn];
    }
    __syncthreads();

    // ---- DP alignment + backtrace (thread 0; 45x31 table) ----
    if (tid == 0) {
        float prev[31], cur[31];
        const float FINF = INFINITY;
        for (int j = 0; j < 31; j++) { prev[j] = FINF; sdir[j] = 0; }
        prev[0] = 0.f;                       // ii=0: 0 < 30
        prev[1] = -scls[0 * NCAND + 0];      // cost[0,0]
        sdir[1] = 1;
        for (int ii = 1; ii < NCAND; ii++) {
            for (int j = 0; j < 31; j++) {
                float dm1 = (j >= 1) ? prev[j - 1] : FINF;
                float dm2 = (j >= 2) ? prev[j - 2] : FINF;
                float nv; signed char nd;
                if (j >= 2) {
                    if ((j & 1) == 0) {
                        nv = fminf(prev[j], dm1);
                        nd = (prev[j] < dm1) ? 0 : 1;
                    } else {
                        int ta = j >> 1; if (ta > NTR - 1) ta = NTR - 1;
                        nv = -scls[ta * NCAND + ii] + fminf(dm1, dm2);
                        nd = (dm1 < dm2) ? 1 : 2;
                    }
                } else if (j == 0) {
                    nv = (ii < NCAND - NTR) ? 0.f : FINF;  // ii < 30
                    nd = 0;
                } else { // j == 1
                    nv = (ii <= NCAND - NTR) ? -scls[0 * NCAND + ii] : FINF;
                    nd = (ii <= NCAND - NTR) ? 1 : 0;
                }
                cur[j] = nv;
                sdir[ii * 31 + j] = nd;
            }
            for (int j = 0; j < 31; j++) prev[j] = cur[j];
        }
        int cj = (prev[30] < prev[29]) ? 30 : 29;
        int outi[NCAND];
        for (int ii = NCAND - 1; ii >= 0; ii--) {
            outi[ii] = (cj & 1) ? (cj >> 1) : NTR;
            cj -= sdir[ii * 31 + cj];
        }
        int res[NTR];
        for (int k = 0; k < NTR; k++) res[k] = 0;
        for (int ii = 0; ii < NCAND; ii++) {
            int oi = outi[ii];
            if (oi < NTR) res[oi] = ii;
        }
        for (int k = 0; k < NTR; k++) sbdy[k] = scand[res[k]];
    }
    __syncthreads();

    // ---- pse + frame CE partial sum (mask is all-true) ----
    float lce = 0.f;
    for (int t = tid; t < TT; t += 256) {
        int cnt = 0;
        #pragma unroll
        for (int j = 0; j < NTR; j++) cnt += (t >= sbdy[j]) ? 1 : 0;
        int cid = s_tr[cnt];
        g_pse[b * TT + t] = cid;
        lce += g_lse[b * TT + t] - fr_logit[(size_t)(b * TT + t) * CC + cid];
    }
    sred[tid] = lce;
    __syncthreads();
    for (int s = 128; s > 0; s >>= 1) {
        if (tid < s) sred[tid] += sred[tid + s];
        __syncthreads();
    }
    if (tid == 0) g_fr_part[b] = sred[0];
}

// ------------------- K6: GLC loss per (b, label-k) -------------------------
__global__ void k6_glc(const float* __restrict__ feat,
                       const int* __restrict__ transcript) {
    __shared__ unsigned char s_match[TT];
    __shared__ float sla[DD];
    __shared__ int s_lab[LL];
    __shared__ float s_sim[CC];
    __shared__ float sred[256];

    int b = blockIdx.x;
    int k = blockIdx.y;
    int tid = threadIdx.x;

    if (tid == 0) {
        int tmp[LL];
        for (int i = 0; i < LL; i++) tmp[i] = transcript[b * LL + i];
        for (int i = 1; i < LL; i++) {
            int v = tmp[i]; int j = i - 1;
            while (j >= 0 && tmp[j] > v) { tmp[j + 1] = tmp[j]; j--; }
            tmp[j + 1] = v;
        }
        for (int i = 0; i < LL; i++) s_lab[i] = tmp[i];
    }
    __syncthreads();
    int label = s_lab[k];

    for (int t = tid; t < TT; t += 256)
        s_match[t] = (g_pse[b * TT + t] == label) ? 1 : 0;
    __syncthreads();

    // label-mean feature (each thread owns dims tid, tid+256)
    float a0 = 0.f, a1 = 0.f;
    int cnt = 0;
    const float* fb = feat + ((size_t)b * (CC + TT) + CC) * DD;
    for (int t = 0; t < TT; t++) {
        if (s_match[t]) {
            a0 += fb[(size_t)t * DD + tid];
            a1 += fb[(size_t)t * DD + tid + 256];
            cnt++;
        }
    }
    float fc = (cnt > 0) ? (float)cnt : 1.f;
    a0 /= fc; a1 /= fc;

    sred[tid] = a0 * a0 + a1 * a1;
    __syncthreads();
    for (int s = 128; s > 0; s >>= 1) {
        if (tid < s) sred[tid] += sred[tid + s];
        __syncthreads();
    }
    float nrm = fmaxf(sqrtf(sred[0]), 1e-12f);
    sla[tid] = a0 / nrm;
    sla[tid + 256] = a1 / nrm;
    __syncthreads();

    // sims vs 48 token rows: 8 warps x 6 rows
    int w = tid >> 5, lane = tid & 31;
    const float* tokb = feat + (size_t)b * (CC + TT) * DD;
    for (int jj = 0; jj < 6; jj++) {
        int j = w * 6 + jj;
        if (j < CC) {
            const float* tkr = tokb + (size_t)j * DD;
            float dot = 0.f, n2 = 0.f;
            for (int d = lane; d < DD; d += 32) {
                float tv = tkr[d];
                dot += sla[d] * tv;
                n2 += tv * tv;
            }
            #pragma unroll
            for (int o = 16; o > 0; o >>= 1) {
                dot += __shfl_xor_sync(0xffffffffu, dot, o);
                n2  += __shfl_xor_sync(0xffffffffu, n2, o);
            }
            if (lane == 0)
                s_sim[j] = dot / (fmaxf(sqrtf(n2), 1e-12f) * 0.1f);
        }
    }
    __syncthreads();

    if (tid == 0) {
        float mx = -INFINITY;
        for (int j = 0; j < CC; j++) mx = fmaxf(mx, s_sim[j]);
        float se = 0.f;
        for (int j = 0; j < CC; j++) se += __expf(s_sim[j] - mx);
        float lse = mx + __logf(se);
        g_glc_part[b * LL + k] = lse - s_sim[label];
    }
}

// ------------------- K7: tok BCE + final combine ---------------------------
__device__ __forceinline__ float log_sigmoid_f(float x) {
    return (x >= 0.f) ? -log1pf(__expf(-x)) : x - log1pf(__expf(x));
}

__global__ void k7_final(const float* __restrict__ tok_logit,
                         const float* __restrict__ y,
                         float* __restrict__ out) {
    __shared__ float sred[256];
    int tid = threadIdx.x;
    float v = 0.f;
    if (tid < BB * CC) {
        float x = tok_logit[tid];
        float yy = y[tid];
        v = -(yy * log_sigmoid_f(x) + (1.f - yy) * log_sigmoid_f(-x));
    }
    sred[tid] = v;
    __syncthreads();
    for (int s = 128; s > 0; s >>= 1) {
        if (tid < s) sred[tid] += sred[tid + s];
        __syncthreads();
    }
    if (tid == 0) {
        float tok = sred[0] / (float)(BB * CC);
        float frs = 0.f;
        for (int b = 0; b < BB; b++) frs += g_fr_part[b];
        float fr = frs / (float)(BB * TT);   // mask all-true -> sum(m) = B*T
        float gs = 0.f;
        for (int i = 0; i < BB * LL; i++) gs += g_glc_part[i];
        float glc = gs / (float)(BB * LL);
        out[0] = tok + fr + 0.1f * glc;
    }
}

// ------------------- launch -------------------------------------------------
extern "C" void kernel_launch(void* const* d_in, const int* in_sizes, int n_in,
                              void* d_out, int out_size) {
    // input order: epoch, tok_logit, fr_logit, mask, transcript, vid_multi_hot, feat
    const float* tok_logit  = (const float*)d_in[1];
    const float* fr_logit   = (const float*)d_in[2];
    const int*   transcript = (const int*)d_in[4];
    const float* vid        = (const float*)d_in[5];
    const float* feat       = (const float*)d_in[6];
    float* out = (float*)d_out;

    k1_softmax<<<(BB * TT) / 8, 256>>>(fr_logit);
    const int ntask = BB * 9 * TP8;
    k2_cross<<<(ntask + 7) / 8, 256>>>();
    k3_score<<<(BB * TT + 255) / 256, 256>>>();
    k4_detect<<<BB, 256>>>(fr_logit, transcript);
    dim3 g6(BB, LL);
    k6_glc<<<g6, 256>>>(feat, transcript);
    k7_final<<<1, 256>>>(tok_logit, vid, out);
}

// round 2
// speedup vs baseline: 1.5141x; 1.5141x over previous
#include <cuda_runtime.h>
#include <math.h>

#define BB 4
#define TT 2048
#define CC 48
#define DD 512
#define LL 16
#define KK 9
#define CSZ 15
#define NTR 15
#define NCAND 45
#define WINLEN 19
#define TP8 (TT + 8)

// ------------------- device scratch (static, no allocs) -------------------
__device__ float g_prob[BB * TT * CC];
__device__ float g_lse[BB * TT];
__device__ float g_ent2[BB * TT];
__device__ float g_cross[BB * 8 * TP8];   // d = 1..8 only (d=0 is analytic)
__device__ float g_score[BB * TT];
__device__ int   g_bdy[BB * NTR];
__device__ float g_fr_part[BB];
__device__ float g_glc_part[BB * LL];

// ------------------- K1: softmax rows + lse + ent2 ------------------------
__global__ void k1_softmax(const float* __restrict__ fr) {
    int gw = (blockIdx.x * blockDim.x + threadIdx.x) >> 5;
    int lane = threadIdx.x & 31;
    if (gw >= BB * TT) return;
    const float* row = fr + (size_t)gw * CC;
    float x0 = row[lane];
    float x1 = (lane < 16) ? row[lane + 32] : -INFINITY;
    float m = fmaxf(x0, x1);
    #pragma unroll
    for (int o = 16; o > 0; o >>= 1) m = fmaxf(m, __shfl_xor_sync(0xffffffffu, m, o));
    float e0 = __expf(x0 - m);
    float e1 = (lane < 16) ? __expf(x1 - m) : 0.f;
    float s = e0 + e1;
    #pragma unroll
    for (int o = 16; o > 0; o >>= 1) s += __shfl_xor_sync(0xffffffffu, s, o);
    float inv = 1.f / s;
    float p0 = e0 * inv, p1 = e1 * inv;
    float ent = (p0 > 0.f) ? p0 * __log2f(p0) : 0.f;
    if (lane < 16) ent += (p1 > 0.f) ? p1 * __log2f(p1) : 0.f;
    #pragma unroll
    for (int o = 16; o > 0; o >>= 1) ent += __shfl_xor_sync(0xffffffffu, ent, o);
    float* pr = g_prob + (size_t)gw * CC;
    pr[lane] = p0;
    if (lane < 16) pr[lane + 32] = p1;
    if (lane == 0) {
        g_lse[gw] = m + __logf(s);
        g_ent2[gw] = ent;
    }
}

// ------------------- K2: crossD[d][rmin], d = 1..8 -------------------------
__global__ void k2_cross() {
    int gw = (blockIdx.x * blockDim.x + threadIdx.x) >> 5;
    int lane = threadIdx.x & 31;
    const int ntask = BB * 8 * TP8;
    if (gw >= ntask) return;
    int b = gw / (8 * TP8);
    int rem = gw % (8 * TP8);
    int d = rem / TP8 + 1;   // 1..8
    int r4 = rem % TP8;
    int r1 = r4 - 4;
    int r2 = r1 + d;
    const float* base = g_prob + (size_t)b * TT * CC;
    float acc = 0.f;
    #pragma unroll
    for (int h = 0; h < 2; h++) {
        int c = lane + 32 * h;
        if (c < CC) {
            float a = (r1 >= 0 && r1 < TT) ? base[r1 * CC + c] : 0.f;
            float bb = (r2 >= 0 && r2 < TT) ? base[r2 * CC + c] : 0.f;
            float sv = a + bb;
            acc += sv * __log2f(0.5f * sv + 1e-32f);
        }
    }
    #pragma unroll
    for (int o = 16; o > 0; o >>= 1) acc += __shfl_xor_sync(0xffffffffu, acc, o);
    if (lane == 0) g_cross[(b * 8 + (d - 1)) * TP8 + r4] = acc;
}

// ------------------- K3: boundary score per (b,t) --------------------------
__global__ void k3_score() {
    int idx = blockIdx.x * blockDim.x + threadIdx.x;
    if (idx >= BB * TT) return;
    int b = idx / TT;
    int t = idx % TT;
    float ent[KK];
    #pragma unroll
    for (int i = 0; i < KK; i++) {
        int r = t - 4 + i;
        ent[i] = (r >= 0 && r < TT) ? g_ent2[b * TT + r] : 0.f;
    }
    const float* cr = g_cross + (size_t)b * 8 * TP8;
    float acc = 8.0f;   // the 8 diagonal (i==j, i!=4) terms each contribute kv*1 = +1
    #pragma unroll
    for (int i = 0; i < KK; i++) {
        #pragma unroll
        for (int j = 0; j < KK; j++) {
            if (i == j) continue;
            float kv = ((i < 4) == (j < 4)) ? 1.f : -1.f;
            int d = (j > i) ? (j - i) : (i - j);
            int rmin = t - 4 + ((i < j) ? i : j);
            float cross = cr[(d - 1) * TP8 + rmin + 4];
            float val = 1.f - (ent[i] + ent[j] - cross);
            acc += kv * val;
        }
    }
    float sc = acc * (1.f / 81.f);
    if (t == 0) sc = -INFINITY;
    g_score[idx] = sc;
}

// ------------------- K4: per-batch detect --------------------------------
__global__ void k4_detect(const float* __restrict__ fr_logit,
                          const int* __restrict__ transcript) {
    __shared__ float ss[TT];
    __shared__ float segv[64];
    __shared__ int   segi[64];
    __shared__ int scand[NCAND];
    __shared__ int s_tr[LL];
    __shared__ float scls[NTR * NCAND];
    __shared__ signed char sdir[NCAND * 31];
    __shared__ int sbdy[NTR];
    __shared__ float sred[256];

    int b = blockIdx.x;
    int tid = threadIdx.x;

    for (int t = tid; t < TT; t += 256) ss[t] = g_score[b * TT + t];
    if (tid < LL) s_tr[tid] = transcript[b * LL + tid];
    __syncthreads();

    // init 64 segment maxima (32 elems each), first-index tie-break
    if (tid < 64) {
        int base = tid * 32;
        float bv = -INFINITY; int bi = base;
        #pragma unroll 4
        for (int k2 = 0; k2 < 32; k2++) {
            float v = ss[base + k2];
            if (v > bv) { bv = v; bi = base + k2; }
        }
        segv[tid] = bv; segi[tid] = bi;
    }
    __syncthreads();

    // ---- warp 0: 45 incremental argmax iterations -------------------------
    if (tid < 32) {
        int lane = tid;
        for (int it = 0; it < NCAND; it++) {
            float v0 = segv[lane], v1 = segv[lane + 32];
            int   i0 = segi[lane], i1 = segi[lane + 32];
            float bv; int bi;
            if (v1 > v0) { bv = v1; bi = i1; } else { bv = v0; bi = i0; }
            #pragma unroll
            for (int o = 16; o > 0; o >>= 1) {
                float ov = __shfl_xor_sync(0xffffffffu, bv, o);
                int   oi = __shfl_xor_sync(0xffffffffu, bi, o);
                if (ov > bv || (ov == bv && oi < bi)) { bv = ov; bi = oi; }
            }
            int pick = bi;
            if (lane == 0) scand[it] = pick;
            // suppress [pick-19, pick+19]
            int lo = pick - WINLEN, hi = pick + WINLEN;
            int p0 = lo + lane;
            if (p0 >= 0 && p0 < TT) ss[p0] = -INFINITY;
            int p1 = lo + 32 + lane;
            if (p1 <= hi && p1 >= 0 && p1 < TT) ss[p1] = -INFINITY;
            __syncwarp();
            // recompute affected segments (<=3), one per lane
            int slo = (lo < 0 ? 0 : lo) >> 5;
            int shi = (hi > TT - 1 ? TT - 1 : hi) >> 5;
            int nseg = shi - slo + 1;
            if (lane < nseg) {
                int s = slo + lane;
                int base = s * 32;
                float nv = -INFINITY; int ni = base;
                #pragma unroll 4
                for (int k2 = 0; k2 < 32; k2++) {
                    float v = ss[base + k2];
                    if (v > nv) { nv = v; ni = base + k2; }
                }
                segv[s] = nv; segi[s] = ni;
            }
            __syncwarp();
        }
        if (lane == 0) {
            // insertion-sort the 45 candidates ascending
            for (int i = 1; i < NCAND; i++) {
                int v = scand[i]; int j = i - 1;
                while (j >= 0 && scand[j] > v) { scand[j + 1] = scand[j]; j--; }
                scand[j + 1] = v;
            }
        }
    }
    __syncthreads();

    // ---- cls matrix --------------------------------------------------------
    const float* pb = g_prob + (size_t)b * TT * CC;
    for (int e = tid; e < NTR * NCAND; e += 256) {
        int tr_i = e / NCAND;
        int n = e % NCAND;
        int cn = scand[n];
        int ca = s_tr[tr_i], cb = s_tr[tr_i + 1];
        float sacc = 0.f;
        #pragma unroll
        for (int sft = 0; sft < CSZ; sft++) {
            int r = cn + sft - 7;
            if (r >= 0 && r < TT) {
                float sign = (sft < 7) ? 1.f : -1.f;
                sacc += sign * (pb[r * CC + ca] - pb[r * CC + cb]);
            }
        }
        scls[e] = sacc * (1.f / 30.f) + g_score[b * TT + cn];
    }
    __syncthreads();

    // ---- DP: 31 lanes, one column each ------------------------------------
    if (tid < 32) {
        int j = tid;
        const float FINF = INFINITY;
        bool active = (j < 31);
        float prev;
        if (j == 0) prev = 0.f;
        else if (j == 1) prev = -scls[0 * NCAND + 0];
        else prev = FINF;
        if (active) sdir[j] = (j == 1) ? 1 : 0;
        int ta = j >> 1; if (ta > NTR - 1) ta = NTR - 1;
        bool even = ((j & 1) == 0);
        for (int ii = 1; ii < NCAND; ii++) {
            float dm1 = __shfl_up_sync(0xffffffffu, prev, 1);
            float dm2 = __shfl_up_sync(0xffffffffu, prev, 2);
            if (j < 1) dm1 = FINF;
            if (j < 2) dm2 = FINF;
            float nv; signed char nd;
            if (j >= 2) {
                if (even) {
                    nv = fminf(prev, dm1);
                    nd = (prev < dm1) ? 0 : 1;
                } else {
                    nv = -scls[ta * NCAND + ii] + fminf(dm1, dm2);
                    nd = (dm1 < dm2) ? 1 : 2;
                }
            } else if (j == 0) {
                nv = (ii < NCAND - NTR) ? 0.f : FINF; nd = 0;
            } else {
                bool ok = (ii <= NCAND - NTR);
                nv = ok ? -scls[0 * NCAND + ii] : FINF;
                nd = ok ? 1 : 0;
            }
            prev = nv;
            if (active) sdir[ii * 31 + j] = nd;
        }
        float p30 = __shfl_sync(0xffffffffu, prev, 30);
        float p29 = __shfl_sync(0xffffffffu, prev, 29);
        if (j == 0) {
            int cj = (p30 < p29) ? 30 : 29;
            int outi[NCAND];
            for (int ii = NCAND - 1; ii >= 0; ii--) {
                outi[ii] = (cj & 1) ? (cj >> 1) : NTR;
                cj -= sdir[ii * 31 + cj];
            }
            int res[NTR];
            #pragma unroll
            for (int k2 = 0; k2 < NTR; k2++) res[k2] = 0;
            for (int ii = 0; ii < NCAND; ii++) {
                int oi = outi[ii];
                if (oi < NTR) res[oi] = ii;
            }
            #pragma unroll
            for (int k2 = 0; k2 < NTR; k2++) {
                sbdy[k2] = scand[res[k2]];
                g_bdy[b * NTR + k2] = scand[res[k2]];
            }
        }
    }
    __syncthreads();

    // ---- pse + frame CE partial sum (mask all-true) ------------------------
    float lce = 0.f;
    for (int t = tid; t < TT; t += 256) {
        int cnt = 0;
        #pragma unroll
        for (int j = 0; j < NTR; j++) cnt += (t >= sbdy[j]) ? 1 : 0;
        int cid = s_tr[cnt];
        lce += g_lse[b * TT + t] - fr_logit[(size_t)(b * TT + t) * CC + cid];
    }
    sred[tid] = lce;
    __syncthreads();
    for (int s = 128; s > 0; s >>= 1) {
        if (tid < s) sred[tid] += sred[tid + s];
        __syncthreads();
    }
    if (tid == 0) g_fr_part[b] = sred[0];
}

// ------------------- K6: GLC loss per (b, sorted-label k) ------------------
__global__ void k6_glc(const float* __restrict__ feat,
                       const int* __restrict__ transcript) {
    __shared__ int s_tr[LL];
    __shared__ int sb[NTR];
    __shared__ int s_m;
    __shared__ float sla[DD];
    __shared__ float s_sim[CC];
    __shared__ float sred[256];

    int b = blockIdx.x;
    int k = blockIdx.y;
    int tid = threadIdx.x;

    if (tid < LL) s_tr[tid] = transcript[b * LL + tid];
    if (tid < NTR) sb[tid] = g_bdy[b * NTR + tid];
    __syncthreads();

    // label = k-th smallest transcript entry; m = its position (distinct labels)
    if (tid < LL) {
        int v = s_tr[tid];
        int rank = 0;
        #pragma unroll
        for (int i = 0; i < LL; i++) rank += (s_tr[i] < v) ? 1 : 0;
        if (rank == k) s_m = tid;
    }
    __syncthreads();
    int m = s_m;
    int label = s_tr[m];
    int lo = (m == 0) ? 0 : sb[m - 1];
    int hi = (m == LL - 1) ? TT : sb[m];
    int cnt = hi - lo;

    // label-mean feature over contiguous frame range [lo, hi)
    float a0 = 0.f, a1 = 0.f;
    const float* fb = feat + ((size_t)b * (CC + TT) + CC) * DD;
    for (int t = lo; t < hi; t++) {
        a0 += fb[(size_t)t * DD + tid];
        a1 += fb[(size_t)t * DD + tid + 256];
    }
    float fc = (cnt > 0) ? (float)cnt : 1.f;
    a0 /= fc; a1 /= fc;

    sred[tid] = a0 * a0 + a1 * a1;
    __syncthreads();
    for (int s = 128; s > 0; s >>= 1) {
        if (tid < s) sred[tid] += sred[tid + s];
        __syncthreads();
    }
    float nrm = fmaxf(sqrtf(sred[0]), 1e-12f);
    sla[tid] = a0 / nrm;
    sla[tid + 256] = a1 / nrm;
    __syncthreads();

    // cosine sims vs the 48 token rows (8 warps x 6 rows)
    int w = tid >> 5, lane = tid & 31;
    const float* tokb = feat + (size_t)b * (CC + TT) * DD;
    for (int jj = 0; jj < 6; jj++) {
        int j = w * 6 + jj;
        if (j < CC) {
            const float* tkr = tokb + (size_t)j * DD;
            float dot = 0.f, n2 = 0.f;
            for (int d = lane; d < DD; d += 32) {
                float tv = tkr[d];
                dot += sla[d] * tv;
                n2 += tv * tv;
            }
            #pragma unroll
            for (int o = 16; o > 0; o >>= 1) {
                dot += __shfl_xor_sync(0xffffffffu, dot, o);
                n2  += __shfl_xor_sync(0xffffffffu, n2, o);
            }
            if (lane == 0)
                s_sim[j] = dot / (fmaxf(sqrtf(n2), 1e-12f) * 0.1f);
        }
    }
    __syncthreads();

    if (tid == 0) {
        float mx = -INFINITY;
        for (int j = 0; j < CC; j++) mx = fmaxf(mx, s_sim[j]);
        float se = 0.f;
        for (int j = 0; j < CC; j++) se += __expf(s_sim[j] - mx);
        float lse = mx + __logf(se);
        g_glc_part[b * LL + k] = lse - s_sim[label];
    }
}

// ------------------- K7: tok BCE + final combine ---------------------------
__device__ __forceinline__ float log_sigmoid_f(float x) {
    return (x >= 0.f) ? -log1pf(__expf(-x)) : x - log1pf(__expf(x));
}

__global__ void k7_final(const float* __restrict__ tok_logit,
                         const float* __restrict__ y,
                         float* __restrict__ out) {
    __shared__ float sred[256];
    int tid = threadIdx.x;
    float v = 0.f;
    if (tid < BB * CC) {
        float x = tok_logit[tid];
        float yy = y[tid];
        v = -(yy * log_sigmoid_f(x) + (1.f - yy) * log_sigmoid_f(-x));
    }
    sred[tid] = v;
    __syncthreads();
    for (int s = 128; s > 0; s >>= 1) {
        if (tid < s) sred[tid] += sred[tid + s];
        __syncthreads();
    }
    if (tid == 0) {
        float tok = sred[0] / (float)(BB * CC);
        float frs = 0.f;
        for (int b = 0; b < BB; b++) frs += g_fr_part[b];
        float fr = frs / (float)(BB * TT);
        float gs = 0.f;
        for (int i = 0; i < BB * LL; i++) gs += g_glc_part[i];
        float glc = gs / (float)(BB * LL);
        out[0] = tok + fr + 0.1f * glc;
    }
}

// ------------------- launch -------------------------------------------------
extern "C" void kernel_launch(void* const* d_in, const int* in_sizes, int n_in,
                              void* d_out, int out_size) {
    const float* tok_logit  = (const float*)d_in[1];
    const float* fr_logit   = (const float*)d_in[2];
    const int*   transcript = (const int*)d_in[4];
    const float* vid        = (const float*)d_in[5];
    const float* feat       = (const float*)d_in[6];
    float* out = (float*)d_out;

    k1_softmax<<<(BB * TT) / 8, 256>>>(fr_logit);
    const int ntask = BB * 8 * TP8;
    k2_cross<<<(ntask + 7) / 8, 256>>>();
    k3_score<<<(BB * TT + 255) / 256, 256>>>();
    k4_detect<<<BB, 256>>>(fr_logit, transcript);
    dim3 g6(BB, LL);
    k6_glc<<<g6, 256>>>(feat, transcript);
    k7_final<<<1, 256>>>(tok_logit, vid, out);
}

// round 3
// speedup vs baseline: 2.2922x; 1.5139x over previous
#include <cuda_runtime.h>
#include <math.h>

#define BB 4
#define TT 2048
#define CC 48
#define DD 512
#define LL 16
#define KK 9
#define CSZ 15
#define NTR 15
#define NCAND 45
#define WINLEN 19
#define TP8 (TT + 8)

// ------------------- device scratch (static, no allocs) -------------------
__device__ float g_prob[BB * TT * CC];
__device__ float g_lse[BB * TT];
__device__ float g_ent2[BB * TT];
__device__ float g_cross[BB * 8 * TP8];   // d = 1..8 (d=0 analytic)
__device__ float g_score[BB * TT];
__device__ int   g_bdy[BB * NTR];
__device__ float g_fr_part[BB];
__device__ float g_glc_part[BB * LL];

// order-preserving float -> uint32 (monotone; suppressed marker 0 is minimal)
__device__ __forceinline__ unsigned f2sortable(float f) {
    unsigned u = __float_as_uint(f);
    return (u & 0x80000000u) ? ~u : (u | 0x80000000u);
}

// Cephes-style fast log2 on the FMA pipe (x > 0, normal)
__device__ __forceinline__ float fast_log2(float x) {
    unsigned u = __float_as_uint(x);
    int e = (int)(u >> 23) - 127;
    u = (u & 0x007fffffu) | 0x3f800000u;
    float m = __uint_as_float(u);
    if (m > 1.4142135f) { m *= 0.5f; e += 1; }
    float z = m - 1.0f;
    float p =          7.0376836292e-2f;
    p = p * z + -1.1514610310e-1f;
    p = p * z +  1.1676998740e-1f;
    p = p * z + -1.2420140846e-1f;
    p = p * z +  1.4249322787e-1f;
    p = p * z + -1.6668057665e-1f;
    p = p * z +  2.0000714765e-1f;
    p = p * z + -2.4999993993e-1f;
    p = p * z +  3.3333331174e-1f;
    float z2 = z * z;
    float y = p * z * z2 - 0.5f * z2 + z;            // ln(m)
    return y * 1.4426950408889634f + (float)e;       // log2(x)
}

// ------------------- K1: softmax rows + lse + ent2 ------------------------
__global__ void k1_softmax(const float* __restrict__ fr) {
    int gw = (blockIdx.x * blockDim.x + threadIdx.x) >> 5;
    int lane = threadIdx.x & 31;
    if (gw >= BB * TT) return;
    const float* row = fr + (size_t)gw * CC;
    float x0 = row[lane];
    float x1 = (lane < 16) ? row[lane + 32] : -INFINITY;
    float m = fmaxf(x0, x1);
    #pragma unroll
    for (int o = 16; o > 0; o >>= 1) m = fmaxf(m, __shfl_xor_sync(0xffffffffu, m, o));
    float e0 = __expf(x0 - m);
    float e1 = (lane < 16) ? __expf(x1 - m) : 0.f;
    float s = e0 + e1;
    #pragma unroll
    for (int o = 16; o > 0; o >>= 1) s += __shfl_xor_sync(0xffffffffu, s, o);
    float inv = 1.f / s;
    float p0 = e0 * inv, p1 = e1 * inv;
    float ent = (p0 > 0.f) ? p0 * __log2f(p0) : 0.f;
    if (lane < 16) ent += (p1 > 0.f) ? p1 * __log2f(p1) : 0.f;
    #pragma unroll
    for (int o = 16; o > 0; o >>= 1) ent += __shfl_xor_sync(0xffffffffu, ent, o);
    float* pr = g_prob + (size_t)gw * CC;
    pr[lane] = p0;
    if (lane < 16) pr[lane + 32] = p1;
    if (lane == 0) {
        g_lse[gw] = m + __logf(s);
        g_ent2[gw] = ent;
    }
}

// ------------------- K2: crossD[d][rmin], d = 1..8, hybrid log pipes -------
__global__ void k2_cross() {
    int gw = (blockIdx.x * blockDim.x + threadIdx.x) >> 5;
    int lane = threadIdx.x & 31;
    const int ntask = BB * 8 * TP8;
    if (gw >= ntask) return;
    int b = gw / (8 * TP8);
    int rem = gw % (8 * TP8);
    int d = rem / TP8 + 1;   // 1..8
    int r4 = rem % TP8;
    int r1 = r4 - 4;
    int r2 = r1 + d;
    const float* base = g_prob + (size_t)b * TT * CC;
    float acc = 0.f;
    bool use_poly = (d & 1);
    #pragma unroll
    for (int h = 0; h < 2; h++) {
        int c = lane + 32 * h;
        if (c < CC) {
            float a  = (r1 >= 0 && r1 < TT) ? base[r1 * CC + c] : 0.f;
            float bb = (r2 >= 0 && r2 < TT) ? base[r2 * CC + c] : 0.f;
            float sv = a + bb;
            float x = 0.5f * sv + 1e-32f;
            float lg = use_poly ? fast_log2(x) : __log2f(x);
            acc += sv * lg;
        }
    }
    #pragma unroll
    for (int o = 16; o > 0; o >>= 1) acc += __shfl_xor_sync(0xffffffffu, acc, o);
    if (lane == 0) g_cross[(b * 8 + (d - 1)) * TP8 + r4] = acc;
}

// ------------------- K3: boundary score per (b,t) --------------------------
__global__ void k3_score() {
    int idx = blockIdx.x * blockDim.x + threadIdx.x;
    if (idx >= BB * TT) return;
    int b = idx / TT;
    int t = idx % TT;
    float ent[KK];
    #pragma unroll
    for (int i = 0; i < KK; i++) {
        int r = t - 4 + i;
        ent[i] = (r >= 0 && r < TT) ? g_ent2[b * TT + r] : 0.f;
    }
    const float* cr = g_cross + (size_t)b * 8 * TP8;
    float acc = 8.0f;   // 8 diagonal (i==j, i!=4) terms contribute +1 each
    #pragma unroll
    for (int i = 0; i < KK; i++) {
        #pragma unroll
        for (int j = 0; j < KK; j++) {
            if (i == j) continue;
            float kv = ((i < 4) == (j < 4)) ? 1.f : -1.f;
            int d = (j > i) ? (j - i) : (i - j);
            int rmin = t - 4 + ((i < j) ? i : j);
            float cross = cr[(d - 1) * TP8 + rmin + 4];
            float val = 1.f - (ent[i] + ent[j] - cross);
            acc += kv * val;
        }
    }
    float sc = acc * (1.f / 81.f);
    if (t == 0) sc = -INFINITY;
    g_score[idx] = sc;
}

// ------------------- K4: per-batch detect --------------------------------
__global__ void k4_detect(const float* __restrict__ fr_logit,
                          const int* __restrict__ transcript) {
    __shared__ unsigned ss[TT];          // sortable scores (0 = suppressed)
    __shared__ int scand[NCAND];
    __shared__ int scand2[NCAND];        // sorted
    __shared__ int s_tr[LL];
    __shared__ float scls[NTR * NCAND];
    __shared__ signed char sdir[NCAND * 31];
    __shared__ int sbdy[NTR];
    __shared__ float sred[8];

    int b = blockIdx.x;
    int tid = threadIdx.x;
    int lane = tid & 31;
    int wrp = tid >> 5;

    for (int t = tid; t < TT; t += 256) ss[t] = f2sortable(g_score[b * TT + t]);
    if (tid < LL) s_tr[tid] = transcript[b * LL + tid];
    __syncthreads();

    // ---- warp 0: 45 incremental argmax iterations + parallel rank sort ----
    if (tid < 32) {
        // register segment maxima: seg lane (slot0), seg lane+32 (slot1)
        unsigned v0 = 0u, v1 = 0u;
        {
            int b0 = lane * 32, b1 = (lane + 32) * 32;
            #pragma unroll
            for (int k2 = 0; k2 < 32; k2++) {
                v0 = max(v0, ss[b0 + k2]);
                v1 = max(v1, ss[b1 + k2]);
            }
        }
        for (int it = 0; it < NCAND; it++) {
            unsigned loc = max(v0, v1);
            unsigned mv = __reduce_max_sync(0xffffffffu, loc);
            unsigned segc = (v0 == mv) ? (unsigned)lane
                          : ((v1 == mv) ? (unsigned)(lane + 32) : 127u);
            unsigned seg = __reduce_min_sync(0xffffffffu, segc);
            unsigned val = ss[seg * 32 + lane];
            unsigned mask = __ballot_sync(0xffffffffu, val == mv);
            int pick = (int)(seg * 32) + (__ffs(mask) - 1);
            if (lane == 0) scand[it] = pick;
            // suppress [pick-19, pick+19]
            int lo = pick - WINLEN, hi = pick + WINLEN;
            int p0 = lo + lane;
            if (p0 >= 0 && p0 < TT) ss[p0] = 0u;
            int p1 = p0 + 32;
            if (p1 <= hi && p1 < TT) ss[p1] = 0u;
            __syncwarp();
            // rescan affected segments (value-only integer max chain)
            int slo = (lo < 0 ? 0 : lo) >> 5;
            int shi = ((hi > TT - 1 ? TT - 1 : hi)) >> 5;
            if (lane >= slo && lane <= shi) {
                int base = lane * 32;
                unsigned nv = 0u;
                #pragma unroll
                for (int k2 = 0; k2 < 32; k2++) nv = max(nv, ss[base + k2]);
                v0 = nv;
            }
            int l1 = lane + 32;
            if (l1 >= slo && l1 <= shi) {
                int base = l1 * 32;
                unsigned nv = 0u;
                #pragma unroll
                for (int k2 = 0; k2 < 32; k2++) nv = max(nv, ss[base + k2]);
                v1 = nv;
            }
            __syncwarp();
        }
        // rank sort: distinct values -> unique ranks
        int c0 = scand[lane];
        int c1 = (lane + 32 < NCAND) ? scand[lane + 32] : 0x7fffffff;
        int r0 = 0, r1 = 0;
        for (int j = 0; j < NCAND; j++) {
            int cj = scand[j];
            r0 += (cj < c0);
            r1 += (cj < c1);
        }
        scand2[r0] = c0;
        if (lane + 32 < NCAND) scand2[r1] = c1;
    }
    __syncthreads();

    // ---- cls matrix --------------------------------------------------------
    const float* pb = g_prob + (size_t)b * TT * CC;
    for (int e = tid; e < NTR * NCAND; e += 256) {
        int tr_i = e / NCAND;
        int n = e % NCAND;
        int cn = scand2[n];
        int ca = s_tr[tr_i], cb = s_tr[tr_i + 1];
        float sacc = 0.f;
        #pragma unroll
        for (int sft = 0; sft < CSZ; sft++) {
            int r = cn + sft - 7;
            if (r >= 0 && r < TT) {
                float sign = (sft < 7) ? 1.f : -1.f;
                sacc += sign * (pb[r * CC + ca] - pb[r * CC + cb]);
            }
        }
        scls[e] = sacc * (1.f / 30.f) + g_score[b * TT + cn];
    }
    __syncthreads();

    // ---- DP: 31 lanes, one column each; backtrace on lane 0 ----------------
    if (tid < 32) {
        int j = lane;
        const float FINF = INFINITY;
        bool active = (j < 31);
        float prev;
        if (j == 0) prev = 0.f;
        else if (j == 1) prev = -scls[0 * NCAND + 0];
        else prev = FINF;
        if (active) sdir[j] = (j == 1) ? 1 : 0;
        int ta = j >> 1; if (ta > NTR - 1) ta = NTR - 1;
        bool even = ((j & 1) == 0);
        for (int ii = 1; ii < NCAND; ii++) {
            float dm1 = __shfl_up_sync(0xffffffffu, prev, 1);
            float dm2 = __shfl_up_sync(0xffffffffu, prev, 2);
            if (j < 1) dm1 = FINF;
            if (j < 2) dm2 = FINF;
            float nv; signed char nd;
            if (j >= 2) {
                if (even) {
                    nv = fminf(prev, dm1);
                    nd = (prev < dm1) ? 0 : 1;
                } else {
                    nv = -scls[ta * NCAND + ii] + fminf(dm1, dm2);
                    nd = (dm1 < dm2) ? 1 : 2;
                }
            } else if (j == 0) {
                nv = (ii < NCAND - NTR) ? 0.f : FINF; nd = 0;
            } else {
                bool ok = (ii <= NCAND - NTR);
                nv = ok ? -scls[0 * NCAND + ii] : FINF;
                nd = ok ? 1 : 0;
            }
            prev = nv;
            if (active) sdir[ii * 31 + j] = nd;
        }
        float p30 = __shfl_sync(0xffffffffu, prev, 30);
        float p29 = __shfl_sync(0xffffffffu, prev, 29);
        if (j == 0) {
            int cj = (p30 < p29) ? 30 : 29;
            int outi[NCAND];
            #pragma unroll
            for (int ii = NCAND - 1; ii >= 0; ii--) {
                outi[ii] = (cj & 1) ? (cj >> 1) : NTR;
                cj -= sdir[ii * 31 + cj];
            }
            int res[NTR];
            #pragma unroll
            for (int k2 = 0; k2 < NTR; k2++) res[k2] = 0;
            #pragma unroll
            for (int ii = 0; ii < NCAND; ii++) {
                int oi = outi[ii];
                if (oi < NTR) res[oi] = ii;
            }
            #pragma unroll
            for (int k2 = 0; k2 < NTR; k2++) {
                int bv = scand2[res[k2]];
                sbdy[k2] = bv;
                g_bdy[b * NTR + k2] = bv;
            }
        }
    }
    __syncthreads();

    // ---- pse + frame CE partial sum (mask all-true) ------------------------
    float lce = 0.f;
    for (int t = tid; t < TT; t += 256) {
        int cnt = 0;
        #pragma unroll
        for (int j = 0; j < NTR; j++) cnt += (t >= sbdy[j]) ? 1 : 0;
        int cid = s_tr[cnt];
        lce += g_lse[b * TT + t] - fr_logit[(size_t)(b * TT + t) * CC + cid];
    }
    #pragma unroll
    for (int o = 16; o > 0; o >>= 1) lce += __shfl_xor_sync(0xffffffffu, lce, o);
    if (lane == 0) sred[wrp] = lce;
    __syncthreads();
    if (tid == 0) {
        float s = 0.f;
        #pragma unroll
        for (int w = 0; w < 8; w++) s += sred[w];
        g_fr_part[b] = s;
    }
}

// ------------------- K6: GLC loss per (b, sorted-label k) ------------------
__global__ void k6_glc(const float* __restrict__ feat,
                       const int* __restrict__ transcript) {
    __shared__ int s_tr[LL];
    __shared__ int sb[NTR];
    __shared__ int s_m;
    __shared__ float sla[DD];
    __shared__ float s_sim[CC];
    __shared__ float sred[256];

    int b = blockIdx.x;
    int k = blockIdx.y;
    int tid = threadIdx.x;

    if (tid < LL) s_tr[tid] = transcript[b * LL + tid];
    if (tid < NTR) sb[tid] = g_bdy[b * NTR + tid];
    __syncthreads();

    if (tid < LL) {
        int v = s_tr[tid];
        int rank = 0;
        #pragma unroll
        for (int i = 0; i < LL; i++) rank += (s_tr[i] < v) ? 1 : 0;
        if (rank == k) s_m = tid;
    }
    __syncthreads();
    int m = s_m;
    int label = s_tr[m];
    int lo = (m == 0) ? 0 : sb[m - 1];
    int hi = (m == LL - 1) ? TT : sb[m];
    int cnt = hi - lo;

    float a0 = 0.f, a1 = 0.f;
    const float* fb = feat + ((size_t)b * (CC + TT) + CC) * DD;
    for (int t = lo; t < hi; t++) {
        a0 += fb[(size_t)t * DD + tid];
        a1 += fb[(size_t)t * DD + tid + 256];
    }
    float fc = (cnt > 0) ? (float)cnt : 1.f;
    a0 /= fc; a1 /= fc;

    sred[tid] = a0 * a0 + a1 * a1;
    __syncthreads();
    for (int s = 128; s > 0; s >>= 1) {
        if (tid < s) sred[tid] += sred[tid + s];
        __syncthreads();
    }
    float nrm = fmaxf(sqrtf(sred[0]), 1e-12f);
    sla[tid] = a0 / nrm;
    sla[tid + 256] = a1 / nrm;
    __syncthreads();

    int w = tid >> 5, lane = tid & 31;
    const float* tokb = feat + (size_t)b * (CC + TT) * DD;
    for (int jj = 0; jj < 6; jj++) {
        int j = w * 6 + jj;
        if (j < CC) {
            const float* tkr = tokb + (size_t)j * DD;
            float dot = 0.f, n2 = 0.f;
            for (int d = lane; d < DD; d += 32) {
                float tv = tkr[d];
                dot += sla[d] * tv;
                n2 += tv * tv;
            }
            #pragma unroll
            for (int o = 16; o > 0; o >>= 1) {
                dot += __shfl_xor_sync(0xffffffffu, dot, o);
                n2  += __shfl_xor_sync(0xffffffffu, n2, o);
            }
            if (lane == 0)
                s_sim[j] = dot / (fmaxf(sqrtf(n2), 1e-12f) * 0.1f);
        }
    }
    __syncthreads();

    if (tid == 0) {
        float mx = -INFINITY;
        for (int j = 0; j < CC; j++) mx = fmaxf(mx, s_sim[j]);
        float se = 0.f;
        for (int j = 0; j < CC; j++) se += __expf(s_sim[j] - mx);
        float lse = mx + __logf(se);
        g_glc_part[b * LL + k] = lse - s_sim[label];
    }
}

// ------------------- K7: tok BCE + final combine ---------------------------
__device__ __forceinline__ float log_sigmoid_f(float x) {
    return (x >= 0.f) ? -log1pf(__expf(-x)) : x - log1pf(__expf(x));
}

__global__ void k7_final(const float* __restrict__ tok_logit,
                         const float* __restrict__ y,
                         float* __restrict__ out) {
    __shared__ float sred[256];
    int tid = threadIdx.x;
    float v = 0.f;
    if (tid < BB * CC) {
        float x = tok_logit[tid];
        float yy = y[tid];
        v = -(yy * log_sigmoid_f(x) + (1.f - yy) * log_sigmoid_f(-x));
    }
    sred[tid] = v;
    __syncthreads();
    for (int s = 128; s > 0; s >>= 1) {
        if (tid < s) sred[tid] += sred[tid + s];
        __syncthreads();
    }
    if (tid == 0) {
        float tok = sred[0] / (float)(BB * CC);
        float frs = 0.f;
        for (int b = 0; b < BB; b++) frs += g_fr_part[b];
        float fr = frs / (float)(BB * TT);
        float gs = 0.f;
        for (int i = 0; i < BB * LL; i++) gs += g_glc_part[i];
        float glc = gs / (float)(BB * LL);
        out[0] = tok + fr + 0.1f * glc;
    }
}

// ------------------- launch -------------------------------------------------
extern "C" void kernel_launch(void* const* d_in, const int* in_sizes, int n_in,
                              void* d_out, int out_size) {
    const float* tok_logit  = (const float*)d_in[1];
    const float* fr_logit   = (const float*)d_in[2];
    const int*   transcript = (const int*)d_in[4];
    const float* vid        = (const float*)d_in[5];
    const float* feat       = (const float*)d_in[6];
    float* out = (float*)d_out;

    k1_softmax<<<(BB * TT) / 8, 256>>>(fr_logit);
    const int ntask = BB * 8 * TP8;
    k2_cross<<<(ntask + 7) / 8, 256>>>();
    k3_score<<<(BB * TT + 255) / 256, 256>>>();
    k4_detect<<<BB, 256>>>(fr_logit, transcript);
    dim3 g6(BB, LL);
    k6_glc<<<g6, 256>>>(feat, transcript);
    k7_final<<<1, 256>>>(tok_logit, vid, out);
}